// round 6
// baseline (speedup 1.0000x reference)
#include <cuda_runtime.h>
#include <cuda_bf16.h>

// Problem constants (fixed by the dataset)
#define NN      50000
#define EE      800000
#define ET      850000          // EE + NN self loops
#define IN_CH   128
#define HC      256
#define HEADS   4
#define NEG_SLOPE 0.2f
#define LN_EPS  1e-5f

// packed fp32x2 helpers (FFMA2 path — 2x fp32 throughput on sm_103a)
#define FMA2(d, a, b, c) \
    asm("fma.rn.f32x2 %0, %1, %2, %3;" : "=l"(d) : "l"(a), "l"(b), "l"(c))
#define PACK2(d, x, y) \
    asm("mov.b64 %0, {%1, %2};" : "=l"(d) : "r"(__float_as_uint(x)), "r"(__float_as_uint(y)))
#define UNPACK2(x, y, d) \
    asm("mov.b64 {%0, %1}, %2;" : "=r"(x), "=r"(y) : "l"(d))

typedef unsigned long long ull;

// ---------------- device scratch (static, no runtime alloc) ----------------
__device__ float g_h[(size_t)NN * HC];       // 51.2 MB  h = x@W
__device__ float g_as[NN * HEADS];           // per-node att_src dot
__device__ float g_ad[NN * HEADS];           // per-node att_dst dot
__device__ int   g_deg[NN];
__device__ int   g_off[NN + 1];
__device__ int   g_cur[NN];
__device__ int   g_src[ET];                  // sorted-by-dst source node ids

// ---------------- K1: init degree = 1 (self loop) ----------------
__global__ void k_init() {
    int i = blockIdx.x * blockDim.x + threadIdx.x;
    if (i < NN) g_deg[i] = 1;
}

// ---------------- K2: histogram of dst ----------------
__global__ void k_hist(const int* __restrict__ ei) {
    int i = blockIdx.x * blockDim.x + threadIdx.x;
    if (i < EE) {
        int dst = ei[EE + i];
        if (dst >= 0 && dst < NN) atomicAdd(&g_deg[dst], 1);
    }
}

// ---------------- K3: single-block exclusive scan ----------------
__global__ void k_scan() {
    __shared__ int s[1024];
    const int CH = (NN + 1023) / 1024;   // 49
    int t = threadIdx.x;
    int base = t * CH;
    int sum = 0;
    for (int j = 0; j < CH; j++) {
        int i = base + j;
        if (i < NN) sum += g_deg[i];
    }
    s[t] = sum;
    __syncthreads();
    for (int o = 1; o < 1024; o <<= 1) {
        int v = (t >= o) ? s[t - o] : 0;
        __syncthreads();
        s[t] += v;
        __syncthreads();
    }
    int run = (t == 0) ? 0 : s[t - 1];
    for (int j = 0; j < CH; j++) {
        int i = base + j;
        if (i < NN) {
            g_off[i] = run;
            g_cur[i] = run;
            run += g_deg[i];
        }
    }
    if (t == 0) g_off[NN] = s[1023];
}

// ---------------- K4: GEMM h = x@W (row-pair FFMA2), 128x128x8 tiles --------
// 256 threads, 8x8 per-thread micro tile = 4 row-pairs x 8 cols.
#define BM 128
#define BN 128
#define BK 8
#define APITCH 132
#define NKT (IN_CH / BK)     // 16 k-tiles

__global__ __launch_bounds__(256) void k_gemm(const float* __restrict__ x,
                                              const float* __restrict__ W,
                                              const float* __restrict__ att_s,
                                              const float* __restrict__ att_d) {
    __shared__ float As[2][BK * APITCH];   // transposed: As[k][row]
    __shared__ float Bs[2][BK * BN];       // Bs[k][col]
    int t  = threadIdx.x;
    int bm = blockIdx.x * BM;
    int bn = blockIdx.y * BN;
    int tx = t & 15;          // col group: cols bn + tx*8 .. +7
    int ty = t >> 4;          // row group: rows bm + ty*8 .. +7
    int ar = t >> 1;          // A-load row 0..127
    int ak = (t & 1) * 4;     // A-load k offset (0 or 4)
    int br = t >> 5;          // B-load k row 0..7
    int bc = (t & 31) * 4;    // B-load col

    ull acc[4][8] = {};       // [row-pair][col], packed fp32

    // preload tile 0
    {
        float4 av = make_float4(0.f, 0.f, 0.f, 0.f);
        int row = bm + ar;
        if (row < NN) av = *(const float4*)(x + (size_t)row * IN_CH + ak);
        As[0][(ak + 0) * APITCH + ar] = av.x;
        As[0][(ak + 1) * APITCH + ar] = av.y;
        As[0][(ak + 2) * APITCH + ar] = av.z;
        As[0][(ak + 3) * APITCH + ar] = av.w;
        *(float4*)(Bs[0] + br * BN + bc) =
            *(const float4*)(W + (size_t)br * HC + bn + bc);
    }
    __syncthreads();

    int buf = 0;
    #pragma unroll
    for (int kt = 0; kt < NKT; kt++) {
        float4 av, bv;
        if (kt < NKT - 1) {
            int kk = (kt + 1) * BK;
            av = make_float4(0.f, 0.f, 0.f, 0.f);
            int row = bm + ar;
            if (row < NN) av = *(const float4*)(x + (size_t)row * IN_CH + kk + ak);
            bv = *(const float4*)(W + (size_t)(kk + br) * HC + bn + bc);
        }
        const float* Ab = As[buf];
        const float* Bb = Bs[buf];
        #pragma unroll
        for (int k = 0; k < BK; k++) {
            ull a0 = *(const ull*)(Ab + k * APITCH + ty * 8);
            ull a1 = *(const ull*)(Ab + k * APITCH + ty * 8 + 2);
            ull a2 = *(const ull*)(Ab + k * APITCH + ty * 8 + 4);
            ull a3 = *(const ull*)(Ab + k * APITCH + ty * 8 + 6);
            float4 b0 = *(const float4*)(Bb + k * BN + tx * 8);
            float4 b1 = *(const float4*)(Bb + k * BN + tx * 8 + 4);
            ull bb[8];
            PACK2(bb[0], b0.x, b0.x);
            PACK2(bb[1], b0.y, b0.y);
            PACK2(bb[2], b0.z, b0.z);
            PACK2(bb[3], b0.w, b0.w);
            PACK2(bb[4], b1.x, b1.x);
            PACK2(bb[5], b1.y, b1.y);
            PACK2(bb[6], b1.z, b1.z);
            PACK2(bb[7], b1.w, b1.w);
            #pragma unroll
            for (int j = 0; j < 8; j++) {
                FMA2(acc[0][j], a0, bb[j], acc[0][j]);
                FMA2(acc[1][j], a1, bb[j], acc[1][j]);
                FMA2(acc[2][j], a2, bb[j], acc[2][j]);
                FMA2(acc[3][j], a3, bb[j], acc[3][j]);
            }
        }
        if (kt < NKT - 1) {
            int nb = buf ^ 1;
            As[nb][(ak + 0) * APITCH + ar] = av.x;
            As[nb][(ak + 1) * APITCH + ar] = av.y;
            As[nb][(ak + 2) * APITCH + ar] = av.z;
            As[nb][(ak + 3) * APITCH + ar] = av.w;
            *(float4*)(Bs[nb] + br * BN + bc) = bv;
            __syncthreads();
            buf = nb;
        }
    }

    // epilogue: unpack row-pairs, store h, fused attention dots
    int head = (bn >> 6) + (tx >> 3);          // which head these 8 cols are in
    int coff = (tx & 7) * 8;                   // channel offset within head
    float4 sa0 = *(const float4*)(att_s + head * 64 + coff);
    float4 sa1 = *(const float4*)(att_s + head * 64 + coff + 4);
    float4 da0 = *(const float4*)(att_d + head * 64 + coff);
    float4 da1 = *(const float4*)(att_d + head * 64 + coff + 4);

    #pragma unroll
    for (int p = 0; p < 4; p++) {
        unsigned int lo[8], hi[8];
        #pragma unroll
        for (int j = 0; j < 8; j++) UNPACK2(lo[j], hi[j], acc[p][j]);
        #pragma unroll
        for (int r = 0; r < 2; r++) {
            float c[8];
            #pragma unroll
            for (int j = 0; j < 8; j++)
                c[j] = __uint_as_float(r ? hi[j] : lo[j]);
            int row = bm + ty * 8 + 2 * p + r;
            if (row < NN) {
                *(float4*)(g_h + (size_t)row * HC + bn + tx * 8)     = *(float4*)(c);
                *(float4*)(g_h + (size_t)row * HC + bn + tx * 8 + 4) = *(float4*)(c + 4);
            }
            float ps = c[0] * sa0.x + c[1] * sa0.y + c[2] * sa0.z + c[3] * sa0.w
                     + c[4] * sa1.x + c[5] * sa1.y + c[6] * sa1.z + c[7] * sa1.w;
            float pd = c[0] * da0.x + c[1] * da0.y + c[2] * da0.z + c[3] * da0.w
                     + c[4] * da1.x + c[5] * da1.y + c[6] * da1.z + c[7] * da1.w;
            ps += __shfl_xor_sync(0xffffffffu, ps, 1);
            ps += __shfl_xor_sync(0xffffffffu, ps, 2);
            ps += __shfl_xor_sync(0xffffffffu, ps, 4);
            pd += __shfl_xor_sync(0xffffffffu, pd, 1);
            pd += __shfl_xor_sync(0xffffffffu, pd, 2);
            pd += __shfl_xor_sync(0xffffffffu, pd, 4);
            if ((tx & 7) == 0 && row < NN) {
                g_as[row * HEADS + head] = ps;
                g_ad[row * HEADS + head] = pd;
            }
        }
    }
}

// ---------------- K6: counting-sort scatter (src permutation only) ----------
__global__ void k_scatter(const int* __restrict__ ei) {
    int i = blockIdx.x * blockDim.x + threadIdx.x;
    if (i >= ET) return;
    int src, dst;
    if (i < EE) { src = ei[i]; dst = ei[EE + i]; }
    else        { src = dst = i - EE; }
    if (src < 0 || src >= NN || dst < 0 || dst >= NN) return;
    int pos = atomicAdd(&g_cur[dst], 1);
    g_src[pos] = src;
}

// ---------------- K7: warp-per-node softmax-aggregate + LN + ELU ------------
// lane owns 8 channels (head = lane>>3). src read via warp-uniform broadcast LDG.
__global__ __launch_bounds__(256) void k_agg(const float* __restrict__ bias,
                                             const float* __restrict__ gamma,
                                             const float* __restrict__ beta,
                                             float* __restrict__ out) {
    int lane = threadIdx.x & 31;
    int n = blockIdx.x * 8 + (threadIdx.x >> 5);
    if (n >= NN) return;
    int start = g_off[n];
    int end   = g_off[n + 1];
    int head  = lane >> 3;
    int cb    = lane * 8;                    // first channel this lane owns
    float ad  = g_ad[n * HEADS + head];      // dst half, fixed per node/head

    float4 acc0 = make_float4(0.f, 0.f, 0.f, 0.f);
    float4 acc1 = make_float4(0.f, 0.f, 0.f, 0.f);
    float wsum = 0.f;

    #pragma unroll 4
    for (int e = start; e < end; e++) {
        int src = __ldg(&g_src[e]);          // warp-uniform broadcast, L1-hit
        float v = __ldg(&g_as[src * HEADS + head]) + ad;
        v = v > 0.f ? v : NEG_SLOPE * v;
        float w = __expf(v);
        wsum += w;
        const float4* hp = (const float4*)(g_h + (size_t)src * HC + cb);
        float4 h0 = __ldg(hp);
        float4 h1 = __ldg(hp + 1);
        acc0.x += w * h0.x; acc0.y += w * h0.y;
        acc0.z += w * h0.z; acc0.w += w * h0.w;
        acc1.x += w * h1.x; acc1.y += w * h1.y;
        acc1.z += w * h1.z; acc1.w += w * h1.w;
    }

    float inv = 1.f / (wsum + 1e-16f);
    float4 b0 = ((const float4*)bias)[lane * 2];
    float4 b1 = ((const float4*)bias)[lane * 2 + 1];
    acc0.x = acc0.x * inv + b0.x; acc0.y = acc0.y * inv + b0.y;
    acc0.z = acc0.z * inv + b0.z; acc0.w = acc0.w * inv + b0.w;
    acc1.x = acc1.x * inv + b1.x; acc1.y = acc1.y * inv + b1.y;
    acc1.z = acc1.z * inv + b1.z; acc1.w = acc1.w * inv + b1.w;

    // LayerNorm over all 256 channels (warp reduce)
    float ss  = acc0.x + acc0.y + acc0.z + acc0.w + acc1.x + acc1.y + acc1.z + acc1.w;
    float ss2 = acc0.x * acc0.x + acc0.y * acc0.y + acc0.z * acc0.z + acc0.w * acc0.w
              + acc1.x * acc1.x + acc1.y * acc1.y + acc1.z * acc1.z + acc1.w * acc1.w;
    #pragma unroll
    for (int o = 16; o; o >>= 1) {
        ss  += __shfl_xor_sync(0xffffffffu, ss,  o);
        ss2 += __shfl_xor_sync(0xffffffffu, ss2, o);
    }
    float mu  = ss * (1.f / (float)HC);
    float var = ss2 * (1.f / (float)HC) - mu * mu;
    float r = rsqrtf(var + LN_EPS);

    float4 g0 = ((const float4*)gamma)[lane * 2];
    float4 g1 = ((const float4*)gamma)[lane * 2 + 1];
    float4 e0 = ((const float4*)beta)[lane * 2];
    float4 e1 = ((const float4*)beta)[lane * 2 + 1];
    float4 o0, o1;
    o0.x = (acc0.x - mu) * r * g0.x + e0.x;
    o0.y = (acc0.y - mu) * r * g0.y + e0.y;
    o0.z = (acc0.z - mu) * r * g0.z + e0.z;
    o0.w = (acc0.w - mu) * r * g0.w + e0.w;
    o1.x = (acc1.x - mu) * r * g1.x + e1.x;
    o1.y = (acc1.y - mu) * r * g1.y + e1.y;
    o1.z = (acc1.z - mu) * r * g1.z + e1.z;
    o1.w = (acc1.w - mu) * r * g1.w + e1.w;
    o0.x = o0.x > 0.f ? o0.x : (__expf(o0.x) - 1.f);
    o0.y = o0.y > 0.f ? o0.y : (__expf(o0.y) - 1.f);
    o0.z = o0.z > 0.f ? o0.z : (__expf(o0.z) - 1.f);
    o0.w = o0.w > 0.f ? o0.w : (__expf(o0.w) - 1.f);
    o1.x = o1.x > 0.f ? o1.x : (__expf(o1.x) - 1.f);
    o1.y = o1.y > 0.f ? o1.y : (__expf(o1.y) - 1.f);
    o1.z = o1.z > 0.f ? o1.z : (__expf(o1.z) - 1.f);
    o1.w = o1.w > 0.f ? o1.w : (__expf(o1.w) - 1.f);
    ((float4*)out)[(size_t)n * 64 + lane * 2]     = o0;
    ((float4*)out)[(size_t)n * 64 + lane * 2 + 1] = o1;
}

// ---------------- launch ----------------
extern "C" void kernel_launch(void* const* d_in, const int* in_sizes, int n_in,
                              void* d_out, int out_size) {
    const float* x     = (const float*)d_in[0];
    const int*   ei    = (const int*)d_in[1];
    const float* W     = (const float*)d_in[2];
    const float* att_s = (const float*)d_in[3];
    const float* att_d = (const float*)d_in[4];
    const float* bias  = (const float*)d_in[5];
    const float* gamma = (const float*)d_in[6];
    const float* beta  = (const float*)d_in[7];
    float*       out   = (float*)d_out;

    k_init<<<(NN + 255) / 256, 256>>>();
    k_hist<<<(EE + 255) / 256, 256>>>(ei);
    k_scan<<<1, 1024>>>();
    dim3 gg((NN + BM - 1) / BM, HC / BN);
    k_gemm<<<gg, 256>>>(x, W, att_s, att_d);
    k_scatter<<<(ET + 255) / 256, 256>>>(ei);
    k_agg<<<(NN + 7) / 8, 256>>>(bias, gamma, beta, out);
}

// round 7
// speedup vs baseline: 1.0550x; 1.0550x over previous
#include <cuda_runtime.h>
#include <cuda_bf16.h>

// Problem constants (fixed by the dataset)
#define NN      50000
#define EE      800000
#define ET      850000          // EE + NN self loops
#define IN_CH   128
#define HC      256
#define HEADS   4
#define NEG_SLOPE 0.2f
#define LN_EPS  1e-5f

// packed fp32x2 helpers (FFMA2 path — 2x fp32 throughput on sm_103a)
#define FMA2(d, a, b, c) \
    asm("fma.rn.f32x2 %0, %1, %2, %3;" : "=l"(d) : "l"(a), "l"(b), "l"(c))
#define PACK2(d, x, y) \
    asm("mov.b64 %0, {%1, %2};" : "=l"(d) : "r"(__float_as_uint(x)), "r"(__float_as_uint(y)))
#define UNPACK2(x, y, d) \
    asm("mov.b64 {%0, %1}, %2;" : "=r"(x), "=r"(y) : "l"(d))

typedef unsigned long long ull;

// ---------------- device scratch (static, no runtime alloc) ----------------
__device__ float g_h[(size_t)NN * HC];       // 51.2 MB  h = x@W
__device__ float g_as[NN * HEADS];           // per-node att_src dot
__device__ float g_ad[NN * HEADS];           // per-node att_dst dot
__device__ int   g_deg[NN];
__device__ int   g_off[NN + 1];
__device__ int   g_cur[NN];
__device__ int   g_src[ET];                  // sorted-by-dst source node ids

// ---------------- K1: init degree = 1 (self loop) ----------------
__global__ void k_init() {
    int i = blockIdx.x * blockDim.x + threadIdx.x;
    if (i < NN) g_deg[i] = 1;
}

// ---------------- K2: histogram of dst ----------------
__global__ void k_hist(const int* __restrict__ ei) {
    int i = blockIdx.x * blockDim.x + threadIdx.x;
    if (i < EE) {
        int dst = ei[EE + i];
        if (dst >= 0 && dst < NN) atomicAdd(&g_deg[dst], 1);
    }
}

// ---------------- K3: single-block exclusive scan ----------------
__global__ void k_scan() {
    __shared__ int s[1024];
    const int CH = (NN + 1023) / 1024;   // 49
    int t = threadIdx.x;
    int base = t * CH;
    int sum = 0;
    for (int j = 0; j < CH; j++) {
        int i = base + j;
        if (i < NN) sum += g_deg[i];
    }
    s[t] = sum;
    __syncthreads();
    for (int o = 1; o < 1024; o <<= 1) {
        int v = (t >= o) ? s[t - o] : 0;
        __syncthreads();
        s[t] += v;
        __syncthreads();
    }
    int run = (t == 0) ? 0 : s[t - 1];
    for (int j = 0; j < CH; j++) {
        int i = base + j;
        if (i < NN) {
            g_off[i] = run;
            g_cur[i] = run;
            run += g_deg[i];
        }
    }
    if (t == 0) g_off[NN] = s[1023];
}

// ---------------- K4: GEMM h = x@W (row-pair FFMA2, double-buffered) --------
// 64x128 block tile, BK=16, 256 threads; micro tile = 4 row-pairs x 4 cols.
// A fragments via warp-uniform LDS.128 (2 wf), B via LDS.128 (4 wf).
#define BM 64
#define BN 128
#define BK 16
#define APITCH 68

__global__ __launch_bounds__(256) void k_gemm(const float* __restrict__ x,
                                              const float* __restrict__ W,
                                              const float* __restrict__ att_s,
                                              const float* __restrict__ att_d) {
    __shared__ float As[2][BK * APITCH];   // transposed: As[k][row]
    __shared__ float Bs[2][BK * BN];       // Bs[k][col]
    int t  = threadIdx.x;
    int bm = blockIdx.x * BM;
    int bn = blockIdx.y * BN;
    int tx = t & 31;          // col group (cols bn + tx*4 .. +3)
    int ty = t >> 5;          // row group (rows ty*8 .. ty*8+7)
    int lr = t >> 2;          // A-load row 0..63
    int lk = (t & 3) * 4;     // A-load k offset
    int wr = t >> 5;          // B-load k row 0..7
    int wc = (t & 31) * 4;    // B-load col

    ull acc[4][4] = {};       // [row-pair][col], packed fp32

    // preload tile 0
    {
        float4 av = make_float4(0.f, 0.f, 0.f, 0.f);
        int row = bm + lr;
        if (row < NN) av = *(const float4*)(x + (size_t)row * IN_CH + lk);
        As[0][(lk + 0) * APITCH + lr] = av.x;
        As[0][(lk + 1) * APITCH + lr] = av.y;
        As[0][(lk + 2) * APITCH + lr] = av.z;
        As[0][(lk + 3) * APITCH + lr] = av.w;
        *(float4*)(Bs[0] + wr * BN + wc) =
            *(const float4*)(W + (size_t)wr * HC + bn + wc);
        *(float4*)(Bs[0] + (wr + 8) * BN + wc) =
            *(const float4*)(W + (size_t)(wr + 8) * HC + bn + wc);
    }
    __syncthreads();

    int buf = 0;
    #pragma unroll
    for (int t8 = 0; t8 < 8; t8++) {
        float4 av, bv0, bv1;
        if (t8 < 7) {
            int kk = (t8 + 1) * BK;
            av = make_float4(0.f, 0.f, 0.f, 0.f);
            int row = bm + lr;
            if (row < NN) av = *(const float4*)(x + (size_t)row * IN_CH + kk + lk);
            bv0 = *(const float4*)(W + (size_t)(kk + wr) * HC + bn + wc);
            bv1 = *(const float4*)(W + (size_t)(kk + wr + 8) * HC + bn + wc);
        }
        const float* Ab = As[buf];
        const float* Bb = Bs[buf];
        #pragma unroll
        for (int k = 0; k < BK; k++) {
            // A row-pairs via two warp-uniform LDS.128 (broadcast, 1 wf each)
            ulonglong2 A0 = *(const ulonglong2*)(Ab + k * APITCH + ty * 8);
            ulonglong2 A1 = *(const ulonglong2*)(Ab + k * APITCH + ty * 8 + 4);
            float4 b = *(const float4*)(Bb + k * BN + tx * 4);
            ull bb0, bb1, bb2, bb3;
            PACK2(bb0, b.x, b.x);
            PACK2(bb1, b.y, b.y);
            PACK2(bb2, b.z, b.z);
            PACK2(bb3, b.w, b.w);
            FMA2(acc[0][0], A0.x, bb0, acc[0][0]);
            FMA2(acc[0][1], A0.x, bb1, acc[0][1]);
            FMA2(acc[0][2], A0.x, bb2, acc[0][2]);
            FMA2(acc[0][3], A0.x, bb3, acc[0][3]);
            FMA2(acc[1][0], A0.y, bb0, acc[1][0]);
            FMA2(acc[1][1], A0.y, bb1, acc[1][1]);
            FMA2(acc[1][2], A0.y, bb2, acc[1][2]);
            FMA2(acc[1][3], A0.y, bb3, acc[1][3]);
            FMA2(acc[2][0], A1.x, bb0, acc[2][0]);
            FMA2(acc[2][1], A1.x, bb1, acc[2][1]);
            FMA2(acc[2][2], A1.x, bb2, acc[2][2]);
            FMA2(acc[2][3], A1.x, bb3, acc[2][3]);
            FMA2(acc[3][0], A1.y, bb0, acc[3][0]);
            FMA2(acc[3][1], A1.y, bb1, acc[3][1]);
            FMA2(acc[3][2], A1.y, bb2, acc[3][2]);
            FMA2(acc[3][3], A1.y, bb3, acc[3][3]);
        }
        if (t8 < 7) {
            int nb = buf ^ 1;
            As[nb][(lk + 0) * APITCH + lr] = av.x;
            As[nb][(lk + 1) * APITCH + lr] = av.y;
            As[nb][(lk + 2) * APITCH + lr] = av.z;
            As[nb][(lk + 3) * APITCH + lr] = av.w;
            *(float4*)(Bs[nb] + wr * BN + wc) = bv0;
            *(float4*)(Bs[nb] + (wr + 8) * BN + wc) = bv1;
            __syncthreads();
            buf = nb;
        }
    }

    // epilogue: unpack row-pairs, store h, fused attention dots
    int head = (bn >> 6) + (tx >> 4);          // 64 cols per head
    int coff = (tx & 15) * 4;                  // channel offset within head
    float4 sa = *(const float4*)(att_s + head * 64 + coff);
    float4 da = *(const float4*)(att_d + head * 64 + coff);

    #pragma unroll
    for (int p = 0; p < 4; p++) {
        unsigned int l0, h0, l1, h1, l2, h2, l3, h3;
        UNPACK2(l0, h0, acc[p][0]);
        UNPACK2(l1, h1, acc[p][1]);
        UNPACK2(l2, h2, acc[p][2]);
        UNPACK2(l3, h3, acc[p][3]);
        float4 c0 = make_float4(__uint_as_float(l0), __uint_as_float(l1),
                                __uint_as_float(l2), __uint_as_float(l3));
        float4 c1 = make_float4(__uint_as_float(h0), __uint_as_float(h1),
                                __uint_as_float(h2), __uint_as_float(h3));
        int row0 = bm + ty * 8 + 2 * p;
        #pragma unroll
        for (int r = 0; r < 2; r++) {
            float4 c = r ? c1 : c0;
            int row = row0 + r;
            if (row < NN)
                *(float4*)(g_h + (size_t)row * HC + bn + tx * 4) = c;
            float ps = c.x * sa.x + c.y * sa.y + c.z * sa.z + c.w * sa.w;
            float pd = c.x * da.x + c.y * da.y + c.z * da.z + c.w * da.w;
            #pragma unroll
            for (int o = 1; o < 16; o <<= 1) {
                ps += __shfl_xor_sync(0xffffffffu, ps, o);
                pd += __shfl_xor_sync(0xffffffffu, pd, o);
            }
            if ((tx & 15) == 0 && row < NN) {
                g_as[row * HEADS + head] = ps;
                g_ad[row * HEADS + head] = pd;
            }
        }
    }
}

// ---------------- K6: counting-sort scatter (src permutation only) ----------
__global__ void k_scatter(const int* __restrict__ ei) {
    int i = blockIdx.x * blockDim.x + threadIdx.x;
    if (i >= ET) return;
    int src, dst;
    if (i < EE) { src = ei[i]; dst = ei[EE + i]; }
    else        { src = dst = i - EE; }
    if (src < 0 || src >= NN || dst < 0 || dst >= NN) return;
    int pos = atomicAdd(&g_cur[dst], 1);
    g_src[pos] = src;
}

// ---------------- K7: warp-per-node softmax-aggregate + LN + ELU ------------
// lane owns 8 channels (head = lane>>3). 2-edge unrolled, loads front-batched.
__global__ __launch_bounds__(256) void k_agg(const float* __restrict__ bias,
                                             const float* __restrict__ gamma,
                                             const float* __restrict__ beta,
                                             float* __restrict__ out) {
    int lane = threadIdx.x & 31;
    int n = blockIdx.x * 8 + (threadIdx.x >> 5);
    if (n >= NN) return;
    int start = g_off[n];
    int end   = g_off[n + 1];
    int head  = lane >> 3;
    int cb    = lane * 8;                    // first channel this lane owns
    float ad  = g_ad[n * HEADS + head];      // dst half, fixed per node/head

    float4 acc0 = make_float4(0.f, 0.f, 0.f, 0.f);
    float4 acc1 = make_float4(0.f, 0.f, 0.f, 0.f);
    float wsum = 0.f;

    int e = start;
    // 2-edge unrolled main loop: batch independent loads before compute
    for (; e + 2 <= end; e += 2) {
        int s0 = __ldg(&g_src[e]);
        int s1 = __ldg(&g_src[e + 1]);
        float v0 = __ldg(&g_as[s0 * HEADS + head]);
        float v1 = __ldg(&g_as[s1 * HEADS + head]);
        const float4* hp0 = (const float4*)(g_h + (size_t)s0 * HC + cb);
        const float4* hp1 = (const float4*)(g_h + (size_t)s1 * HC + cb);
        float4 p0 = __ldg(hp0);
        float4 p1 = __ldg(hp0 + 1);
        float4 q0 = __ldg(hp1);
        float4 q1 = __ldg(hp1 + 1);
        v0 += ad; v0 = v0 > 0.f ? v0 : NEG_SLOPE * v0;
        v1 += ad; v1 = v1 > 0.f ? v1 : NEG_SLOPE * v1;
        float w0 = __expf(v0);
        float w1 = __expf(v1);
        wsum += w0 + w1;
        acc0.x += w0 * p0.x; acc0.y += w0 * p0.y;
        acc0.z += w0 * p0.z; acc0.w += w0 * p0.w;
        acc1.x += w0 * p1.x; acc1.y += w0 * p1.y;
        acc1.z += w0 * p1.z; acc1.w += w0 * p1.w;
        acc0.x += w1 * q0.x; acc0.y += w1 * q0.y;
        acc0.z += w1 * q0.z; acc0.w += w1 * q0.w;
        acc1.x += w1 * q1.x; acc1.y += w1 * q1.y;
        acc1.z += w1 * q1.z; acc1.w += w1 * q1.w;
    }
    if (e < end) {
        int s0 = __ldg(&g_src[e]);
        float v0 = __ldg(&g_as[s0 * HEADS + head]) + ad;
        v0 = v0 > 0.f ? v0 : NEG_SLOPE * v0;
        float w0 = __expf(v0);
        wsum += w0;
        const float4* hp0 = (const float4*)(g_h + (size_t)s0 * HC + cb);
        float4 p0 = __ldg(hp0);
        float4 p1 = __ldg(hp0 + 1);
        acc0.x += w0 * p0.x; acc0.y += w0 * p0.y;
        acc0.z += w0 * p0.z; acc0.w += w0 * p0.w;
        acc1.x += w0 * p1.x; acc1.y += w0 * p1.y;
        acc1.z += w0 * p1.z; acc1.w += w0 * p1.w;
    }

    float inv = 1.f / (wsum + 1e-16f);
    float4 b0 = ((const float4*)bias)[lane * 2];
    float4 b1 = ((const float4*)bias)[lane * 2 + 1];
    acc0.x = acc0.x * inv + b0.x; acc0.y = acc0.y * inv + b0.y;
    acc0.z = acc0.z * inv + b0.z; acc0.w = acc0.w * inv + b0.w;
    acc1.x = acc1.x * inv + b1.x; acc1.y = acc1.y * inv + b1.y;
    acc1.z = acc1.z * inv + b1.z; acc1.w = acc1.w * inv + b1.w;

    // LayerNorm over all 256 channels (warp reduce)
    float ss  = acc0.x + acc0.y + acc0.z + acc0.w + acc1.x + acc1.y + acc1.z + acc1.w;
    float ss2 = acc0.x * acc0.x + acc0.y * acc0.y + acc0.z * acc0.z + acc0.w * acc0.w
              + acc1.x * acc1.x + acc1.y * acc1.y + acc1.z * acc1.z + acc1.w * acc1.w;
    #pragma unroll
    for (int o = 16; o; o >>= 1) {
        ss  += __shfl_xor_sync(0xffffffffu, ss,  o);
        ss2 += __shfl_xor_sync(0xffffffffu, ss2, o);
    }
    float mu  = ss * (1.f / (float)HC);
    float var = ss2 * (1.f / (float)HC) - mu * mu;
    float r = rsqrtf(var + LN_EPS);

    float4 g0 = ((const float4*)gamma)[lane * 2];
    float4 g1 = ((const float4*)gamma)[lane * 2 + 1];
    float4 e0 = ((const float4*)beta)[lane * 2];
    float4 e1 = ((const float4*)beta)[lane * 2 + 1];
    float4 o0, o1;
    o0.x = (acc0.x - mu) * r * g0.x + e0.x;
    o0.y = (acc0.y - mu) * r * g0.y + e0.y;
    o0.z = (acc0.z - mu) * r * g0.z + e0.z;
    o0.w = (acc0.w - mu) * r * g0.w + e0.w;
    o1.x = (acc1.x - mu) * r * g1.x + e1.x;
    o1.y = (acc1.y - mu) * r * g1.y + e1.y;
    o1.z = (acc1.z - mu) * r * g1.z + e1.z;
    o1.w = (acc1.w - mu) * r * g1.w + e1.w;
    o0.x = o0.x > 0.f ? o0.x : (__expf(o0.x) - 1.f);
    o0.y = o0.y > 0.f ? o0.y : (__expf(o0.y) - 1.f);
    o0.z = o0.z > 0.f ? o0.z : (__expf(o0.z) - 1.f);
    o0.w = o0.w > 0.f ? o0.w : (__expf(o0.w) - 1.f);
    o1.x = o1.x > 0.f ? o1.x : (__expf(o1.x) - 1.f);
    o1.y = o1.y > 0.f ? o1.y : (__expf(o1.y) - 1.f);
    o1.z = o1.z > 0.f ? o1.z : (__expf(o1.z) - 1.f);
    o1.w = o1.w > 0.f ? o1.w : (__expf(o1.w) - 1.f);
    ((float4*)out)[(size_t)n * 64 + lane * 2]     = o0;
    ((float4*)out)[(size_t)n * 64 + lane * 2 + 1] = o1;
}

// ---------------- launch ----------------
extern "C" void kernel_launch(void* const* d_in, const int* in_sizes, int n_in,
                              void* d_out, int out_size) {
    const float* x     = (const float*)d_in[0];
    const int*   ei    = (const int*)d_in[1];
    const float* W     = (const float*)d_in[2];
    const float* att_s = (const float*)d_in[3];
    const float* att_d = (const float*)d_in[4];
    const float* bias  = (const float*)d_in[5];
    const float* gamma = (const float*)d_in[6];
    const float* beta  = (const float*)d_in[7];
    float*       out   = (float*)d_out;

    k_init<<<(NN + 255) / 256, 256>>>();
    k_hist<<<(EE + 255) / 256, 256>>>(ei);
    k_scan<<<1, 1024>>>();
    dim3 gg((NN + BM - 1) / BM, HC / BN);
    k_gemm<<<gg, 256>>>(x, W, att_s, att_d);
    k_scatter<<<(ET + 255) / 256, 256>>>(ei);
    k_agg<<<(NN + 7) / 8, 256>>>(bias, gamma, beta, out);
}